// round 6
// baseline (speedup 1.0000x reference)
#include <cuda_runtime.h>
#include <cstdint>

// CTC forward, scaled linear-domain FP64 forward algorithm.
// One CTA per batch element, one thread per extended-label state.
// SYMMETRIC threads: each thread prefetches its OWN logp[t, lbl] via a
// depth-6 register queue (label fixed per thread -> static addresses),
// does its own ex2, computes its state. alpha f64 in smem, double-buffered,
// one barrier per step. Power-of-2 rescale every 64 steps (exact), integer
// exponent accumulator Z. Batch mean folded in via last-CTA atomic.

#define T_DIM 2000
#define V_DIM 256
#define S_DIM 400
#define L_DIM 801
#define NTHREADS 832        // 26 warps
#define KEXP 850
#define RMASK 63
#define QD 6                // logp prefetch depth (rows ahead)

__device__ float g_partial[64];
__device__ int   g_ctr = 0;

__device__ __forceinline__ float ex2f(float x) {
    float y; asm("ex2.approx.f32 %0, %1;" : "=f"(y) : "f"(x)); return y;
}
__device__ __forceinline__ float lg2f(float x) {
    float y; asm("lg2.approx.f32 %0, %1;" : "=f"(y) : "f"(x)); return y;
}

__global__ __launch_bounds__(NTHREADS, 1)
void ctc_kernel(const float* __restrict__ logp,
                const int*   __restrict__ targets,
                const int*   __restrict__ ilen,
                const int*   __restrict__ tlen,
                float*       __restrict__ out,
                int B)
{
    __shared__ double alpha[2][NTHREADS + 2];   // +2 front guard (always 0)
    __shared__ int    wmax[26];
    __shared__ double Cslot;

    const int b   = blockIdx.x;
    const int tid = threadIdx.x;
    const float* lpb = logp + (size_t)b * T_DIM * V_DIM;
    const int il  = ilen[b];
    const int tl  = tlen[b];
    const int end = 2 * tl;

    // per-thread label, skip multiplier, validity mask
    int    lbl   = 1;            // BLANK
    double skipm = 0.0;
    if ((tid & 1) && tid < L_DIM) {
        lbl = targets[b * S_DIM + (tid >> 1)];
        if (tid >= 3 && lbl != targets[b * S_DIM + ((tid - 2) >> 1)]) skipm = 1.0;
    }
    const float vmaskf = (tid < L_DIM && tid <= end) ? 1.0f : 0.0f;
    const float l2e = 1.4426950408889634f;
    const float* gp = lpb + lbl;          // per-thread column pointer
    const int lim = il - 1;               // last row index used

    // zero both alpha buffers (incl. guards)
    for (int i = tid; i < 2 * (NTHREADS + 2); i += NTHREADS)
        ((double*)alpha)[i] = 0.0;

    // t = 0 init values (states 0,1)
    const double K2 = __longlong_as_double(((long long)(KEXP + 1023)) << 52);
    double myv = 0.0;
    if (tid == 0) myv = (double)ex2f(lpb[1]   * l2e) * K2;
    if (tid == 1) myv = (double)ex2f(lpb[lbl] * l2e) * K2;
    __syncthreads();                       // zeroing done
    if (tid < 2) alpha[0][2 + tid] = myv;
    {
        unsigned mm = __reduce_max_sync(0xffffffffu, (unsigned)__double2hiint(myv));
        if ((tid & 31) == 0) wmax[tid >> 5] = (int)mm;
    }
    __syncthreads();                       // wmax + alpha0 visible

    int Z = KEXP;                          // meaningful in thread 800 only
    if (tid >= 800) {                      // warp 25 reduces
        int la = tid - 800;
        unsigned v = (la < 26) ? (unsigned)wmax[la] : 0u;
        unsigned m = __reduce_max_sync(0xffffffffu, v);
        if (tid == 800) {
            int e  = (int)(m >> 20) - 1023;
            int sh = KEXP - e;
            sh = max(-1000, min(1000, sh));
            Cslot = __longlong_as_double(((long long)(sh + 1023)) << 52);
            if (il > 1) Z += sh;
        }
    }

    // logp prefetch queue: rows 1..6 (for steps 1..6), clamped
    float q0, q1, q2, q3, q4, q5;
    q0 = gp[(size_t)min(1, lim) * V_DIM];
    q1 = gp[(size_t)min(2, lim) * V_DIM];
    q2 = gp[(size_t)min(3, lim) * V_DIM];
    q3 = gp[(size_t)min(4, lim) * V_DIM];
    q4 = gp[(size_t)min(5, lim) * V_DIM];
    q5 = gp[(size_t)min(6, lim) * V_DIM];
    __syncthreads();                       // Cslot visible

    // ---- main recursion t = 1 .. il-1, one barrier per step ----
    for (int t = 1; t < il; ++t) {
        double* prev = &alpha[(t + 1) & 1][2];
        double* cur  = &alpha[t & 1][2];

        float  pf = ex2f(q0 * l2e) * vmaskf;    // own prob, masked
        double pd = (double)pf;
        if ((t & RMASK) == 1) pd *= Cslot;      // apply rescale factor

        double a  = prev[tid];
        double a1 = prev[tid - 1];
        double a2 = prev[tid - 2];
        double nv = fma(a2, skipm, a + a1) * pd;
        cur[tid] = nv;

        // rotate prefetch queue, issue next row (clamped, branchless)
        q0 = q1; q1 = q2; q2 = q3; q3 = q4; q4 = q5;
        {
            int rr = t + QD;
            rr = rr < lim ? rr : lim;
            q5 = gp[(size_t)rr * V_DIM];
        }

        if ((t & RMASK) == 0) {                 // measure block max
            unsigned mm = __reduce_max_sync(0xffffffffu,
                                            (unsigned)__double2hiint(nv));
            if ((tid & 31) == 0) wmax[tid >> 5] = (int)mm;
        }
        __syncthreads();

        if ((t & RMASK) == 0) {                 // reducer: scale for t+1
            if (tid >= 800) {
                int la = tid - 800;
                unsigned v = (la < 26) ? (unsigned)wmax[la] : 0u;
                unsigned m = __reduce_max_sync(0xffffffffu, v);
                if (tid == 800) {
                    int e  = (int)(m >> 20) - 1023;
                    int sh = KEXP - e;
                    sh = max(-1000, min(1000, sh));
                    Cslot = __longlong_as_double(((long long)(sh + 1023)) << 52);
                    if (t + 1 < il) Z += sh;
                }
            }
            __syncthreads();
        }
    }

    // ---- epilogue (thread 800 holds Z) ----
    if (tid == 800) {
        double* fin = &alpha[(il - 1) & 1][2];
        double ssum = fin[end] + fin[end - 1];
        float loss;
        if (ssum <= 0.0) {
            loss = 0.0f;
        } else {
            long long bits = __double_as_longlong(ssum);
            int e2 = (int)((unsigned long long)bits >> 52) - 1023;
            double mant = __longlong_as_double((bits & 0x000FFFFFFFFFFFFFLL)
                                               | 0x3FF0000000000000LL);
            double ll = 0.6931471805599453 *
                        ((double)e2 + (double)lg2f((float)mant) - (double)Z);
            loss = (float)(-ll);
            if (!(loss < 1e29f)) loss = 0.0f;
        }
        g_partial[b] = loss / (float)tl;
        __threadfence();
        int done = atomicAdd(&g_ctr, 1);
        if (done == B - 1) {                 // last CTA: final mean + reset
            float v = 0.0f;
            for (int i = 0; i < B; ++i) v += g_partial[i];
            out[0] = v / (float)B;
            g_ctr = 0;                       // deterministic across replays
        }
    }
}

extern "C" void kernel_launch(void* const* d_in, const int* in_sizes, int n_in,
                              void* d_out, int out_size)
{
    const float* logp    = (const float*)d_in[0];
    const int*   targets = (const int*)d_in[1];
    const int*   il      = (const int*)d_in[2];
    const int*   tl      = (const int*)d_in[3];
    const int B = in_sizes[2];

    ctc_kernel<<<B, NTHREADS>>>(logp, targets, il, tl, (float*)d_out, B);
}

// round 7
// speedup vs baseline: 5.6598x; 5.6598x over previous
#include <cuda_runtime.h>
#include <cstdint>

// CTC forward in LOG2 domain, pure f32 (no FP64 anywhere).
// One CTA per batch element, one thread per extended-label state (L=801).
// alpha (log2-prob) in smem f32, double-buffered, one barrier per step.
// Each thread prefetches its OWN logp[t,lbl] (label fixed per thread)
// through a depth-6 register queue. No rescaling needed in log domain.
// Batch mean folded in via last-CTA atomic counter.

#define T_DIM 2000
#define V_DIM 256
#define S_DIM 400
#define L_DIM 801
#define NTHREADS 832        // 26 warps
#define QD 6                // logp prefetch depth (rows ahead)
#define NEGF (-1e30f)

__device__ float g_partial[64];
__device__ int   g_ctr = 0;

__device__ __forceinline__ float ex2f(float x) {
    float y; asm("ex2.approx.f32 %0, %1;" : "=f"(y) : "f"(x)); return y;
}
__device__ __forceinline__ float lg2f(float x) {
    float y; asm("lg2.approx.f32 %0, %1;" : "=f"(y) : "f"(x)); return y;
}

__global__ __launch_bounds__(NTHREADS, 1)
void ctc_kernel(const float* __restrict__ logp,
                const int*   __restrict__ targets,
                const int*   __restrict__ ilen,
                const int*   __restrict__ tlen,
                float*       __restrict__ out,
                int B)
{
    __shared__ float alpha[2][NTHREADS + 2];   // +2 front guard (NEGF)

    const int b   = blockIdx.x;
    const int tid = threadIdx.x;
    const float* lpb = logp + (size_t)b * T_DIM * V_DIM;
    const int il  = ilen[b];
    const int tl  = tlen[b];
    const int end = 2 * tl;
    const float l2e = 1.4426950408889634f;

    // per-thread label / skip / validity
    int  lbl  = 1;                 // BLANK
    bool skip = false;
    if ((tid & 1) && tid < L_DIM) {
        lbl = targets[b * S_DIM + (tid >> 1)];
        if (tid >= 3) skip = (lbl != targets[b * S_DIM + ((tid - 2) >> 1)]);
    }
    const bool valid = (tid < L_DIM) && (tid <= end);
    const float* gp = lpb + lbl;   // per-thread column pointer
    const int lim = il - 1;        // last row index used

    // fill both alpha buffers (incl. guards) with NEGF
    for (int i = tid; i < 2 * (NTHREADS + 2); i += NTHREADS)
        ((float*)alpha)[i] = NEGF;
    __syncthreads();

    // ---- t = 0 init (log2 domain): alpha0[0]=lp2(0,blank), alpha0[1]=lp2(0,l1)
    if (tid == 0) alpha[0][2] = lpb[1]   * l2e;
    if (tid == 1 && valid) alpha[0][3] = lpb[lbl] * l2e;

    // logp prefetch queue: rows 1..QD (clamped)
    float q0, q1, q2, q3, q4, q5;
    q0 = gp[(size_t)min(1, lim) * V_DIM];
    q1 = gp[(size_t)min(2, lim) * V_DIM];
    q2 = gp[(size_t)min(3, lim) * V_DIM];
    q3 = gp[(size_t)min(4, lim) * V_DIM];
    q4 = gp[(size_t)min(5, lim) * V_DIM];
    q5 = gp[(size_t)min(6, lim) * V_DIM];
    __syncthreads();

    // ---- main recursion t = 1 .. il-1, one barrier per step ----
    for (int t = 1; t < il; ++t) {
        const float* prev = &alpha[(t + 1) & 1][2];
        float*       cur  = &alpha[t & 1][2];

        float a  = prev[tid];
        float a1 = prev[tid - 1];
        float a2 = skip ? prev[tid - 2] : NEGF;

        float m  = fmaxf(fmaxf(a, a1), a2);
        float s  = ex2f(a - m) + ex2f(a1 - m) + ex2f(a2 - m);
        float nv = m + lg2f(s) + q0 * l2e;
        nv = valid ? nv : NEGF;
        cur[tid] = nv;

        // rotate prefetch queue, issue next row (clamped, branchless)
        q0 = q1; q1 = q2; q2 = q3; q3 = q4; q4 = q5;
        {
            int rr = t + QD;
            rr = rr < lim ? rr : lim;
            q5 = gp[(size_t)rr * V_DIM];
        }
        __syncthreads();
    }

    // ---- epilogue: ll2 = logaddexp2(fin[end], fin[end-1]) ----
    if (tid == 0) {
        const float* fin = &alpha[(il - 1) & 1][2];
        float x = fin[end], y = fin[end - 1];
        float m = fmaxf(x, y);
        float ll2 = m + lg2f(ex2f(x - m) + ex2f(y - m));
        float loss = -0.6931471805599453f * ll2;
        if (!(loss < 1e29f)) loss = 0.0f;     // catches inf/NaN/infeasible
        g_partial[b] = loss / (float)tl;
        __threadfence();
        int done = atomicAdd(&g_ctr, 1);
        if (done == B - 1) {                  // last CTA: final mean + reset
            float v = 0.0f;
            for (int i = 0; i < B; ++i) v += g_partial[i];
            out[0] = v / (float)B;
            g_ctr = 0;                        // deterministic across replays
        }
    }
}

extern "C" void kernel_launch(void* const* d_in, const int* in_sizes, int n_in,
                              void* d_out, int out_size)
{
    const float* logp    = (const float*)d_in[0];
    const int*   targets = (const int*)d_in[1];
    const int*   il      = (const int*)d_in[2];
    const int*   tl      = (const int*)d_in[3];
    const int B = in_sizes[2];

    ctc_kernel<<<B, NTHREADS>>>(logp, targets, il, tl, (float*)d_out, B);
}